// round 9
// baseline (speedup 1.0000x reference)
#include <cuda_runtime.h>
#include <cuda_fp16.h>
#include <cstdint>

// Problem: x [8,256,256,256] fp32, W [256,256], b [256]
//   u = x[:,:128], v = x[:,128:]; per-batch LayerNorm(v); v@W^T+b; out=u*(v+1)
// LayerNorm deferred to epilogue: vnorm@W^T = rstd*(v@W^T) - mean*rstd*rowsum(W)
#define B_              8
#define WD              256
#define ROWS_PER_BATCH  32768
#define M_TOTAL         262144
#define NV              8388608
#define BATCH_STRIDE    (2 * NV)
#define NCHUNK          512
#define EPS             1e-5f

#define BM   64           // rows per CTA
#define BN   256          // cols per CTA (full width -> v read ONCE)
#define NT   256          // 8 warps
#define KCH  32           // B k-chunk
#define NCH  8            // 256/32 chunks

// SMEM (bytes): c1 (256 f32), A resident 64x256 fp16 (32KB), B 3-stage 16KB each
#define SMEM_C1    0
#define SMEM_A     1024
#define SMEM_BS(s) (1024 + 32768 + (s) * 16384)
#define SMEM_TOTAL (1024 + 32768 + 3 * 16384)   // 82944; x2 CTA/SM fits 228KB

// ---------------- device scratch ----------------
__device__ float  g_partS[B_ * NCHUNK];
__device__ float  g_partQ[B_ * NCHUNK];
__device__ float  g_mean[B_];
__device__ float  g_rstd[B_];
__device__ float  g_Wsum[WD];
__device__ __half g_Wh[WD * WD];

// ---------------- helpers ----------------
__device__ __forceinline__ uint32_t smem_u32(const void* p) {
    uint32_t a;
    asm("{ .reg .u64 t; cvta.to.shared.u64 t, %1; cvt.u32.u64 %0, t; }"
        : "=r"(a) : "l"(p));
    return a;
}
__device__ __forceinline__ uint32_t pack_f16x2(float lo, float hi) {
    uint32_t r;
    asm("cvt.rn.f16x2.f32 %0, %1, %2;" : "=r"(r) : "f"(hi), "f"(lo));
    return r;
}
__device__ __forceinline__ void cp16(uint32_t dst, const void* src) {
    asm volatile("cp.async.cg.shared.global [%0], [%1], 16;" :: "r"(dst), "l"(src));
}
#define CP_COMMIT() asm volatile("cp.async.commit_group;" ::: "memory")
#define CP_WAIT(n)  asm volatile("cp.async.wait_group %0;" :: "n"(n) : "memory")
__device__ __forceinline__ void ldsm_x4(uint32_t& r0, uint32_t& r1, uint32_t& r2,
                                        uint32_t& r3, uint32_t addr) {
    asm volatile("ldmatrix.sync.aligned.m8n8.x4.shared.b16 {%0,%1,%2,%3}, [%4];"
                 : "=r"(r0), "=r"(r1), "=r"(r2), "=r"(r3) : "r"(addr));
}
__device__ __forceinline__ void mma16816(float* d, const uint32_t* a,
                                         uint32_t b0, uint32_t b1) {
    asm volatile(
        "mma.sync.aligned.m16n8k16.row.col.f32.f16.f16.f32 "
        "{%0,%1,%2,%3}, {%4,%5,%6,%7}, {%8,%9}, {%0,%1,%2,%3};"
        : "+f"(d[0]), "+f"(d[1]), "+f"(d[2]), "+f"(d[3])
        : "r"(a[0]), "r"(a[1]), "r"(a[2]), "r"(a[3]), "r"(b0), "r"(b1));
}

// ---------------- W prep: fp16 convert + row sums (tiny) ----------------
__global__ __launch_bounds__(256) void w_prep_kernel(const float* __restrict__ W) {
    const int o = blockIdx.x, t = threadIdx.x;
    float w = W[o * WD + t];
    g_Wh[o * WD + t] = __float2half_rn(w);
    float s = w;
#pragma unroll
    for (int off = 16; off > 0; off >>= 1) s += __shfl_xor_sync(0xffffffffu, s, off);
    __shared__ float ss[8];
    if ((t & 31) == 0) ss[t >> 5] = s;
    __syncthreads();
    if (t == 0) {
        float S = 0.f;
#pragma unroll
        for (int w8 = 0; w8 < 8; w8++) S += ss[w8];
        g_Wsum[o] = S;
    }
}

// ---------------- pass 1: per-(batch,chunk) stats (stats only) ----------------
__global__ __launch_bounds__(256) void reduce_pass1(const float* __restrict__ x) {
    const int b = blockIdx.y;
    const int chunk = blockIdx.x;
    const float4* v4 =
        reinterpret_cast<const float4*>(x + (size_t)b * BATCH_STRIDE + NV);
    const int base = chunk * 4096 + threadIdx.x;
    float s = 0.f, q = 0.f;
#pragma unroll
    for (int i = 0; i < 16; i++) {
        float4 t = v4[base + i * 256];
        s += (t.x + t.y) + (t.z + t.w);
        q += t.x * t.x + t.y * t.y + t.z * t.z + t.w * t.w;
    }
#pragma unroll
    for (int off = 16; off > 0; off >>= 1) {
        s += __shfl_xor_sync(0xffffffffu, s, off);
        q += __shfl_xor_sync(0xffffffffu, q, off);
    }
    __shared__ float ss[8], qs[8];
    const int warp = threadIdx.x >> 5, lane = threadIdx.x & 31;
    if (lane == 0) { ss[warp] = s; qs[warp] = q; }
    __syncthreads();
    if (threadIdx.x == 0) {
        float S = 0.f, Q = 0.f;
#pragma unroll
        for (int w = 0; w < 8; w++) { S += ss[w]; Q += qs[w]; }
        g_partS[b * NCHUNK + chunk] = S;
        g_partQ[b * NCHUNK + chunk] = Q;
    }
}

__global__ __launch_bounds__(256) void reduce_pass2() {
    const int b = blockIdx.x;
    float s = g_partS[b * NCHUNK + threadIdx.x] +
              g_partS[b * NCHUNK + 256 + threadIdx.x];
    float q = g_partQ[b * NCHUNK + threadIdx.x] +
              g_partQ[b * NCHUNK + 256 + threadIdx.x];
#pragma unroll
    for (int off = 16; off > 0; off >>= 1) {
        s += __shfl_xor_sync(0xffffffffu, s, off);
        q += __shfl_xor_sync(0xffffffffu, q, off);
    }
    __shared__ float ss[8], qs[8];
    const int warp = threadIdx.x >> 5, lane = threadIdx.x & 31;
    if (lane == 0) { ss[warp] = s; qs[warp] = q; }
    __syncthreads();
    if (threadIdx.x == 0) {
        float S = 0.f, Q = 0.f;
#pragma unroll
        for (int w = 0; w < 8; w++) { S += ss[w]; Q += qs[w]; }
        const float inv_n = 1.0f / (float)NV;
        float mean = S * inv_n;
        float var = Q * inv_n - mean * mean;
        g_mean[b] = mean;
        g_rstd[b] = rsqrtf(var + EPS);
    }
}

// ---------------- fused GEMM + gating ----------------
// CTA 64x256, 8 warps (warp tile 32x64), 2 CTAs/SM.
// A (64x256 fp16) converted once, smem-resident. B streamed in 8 k=32 chunks,
// 3-stage cp.async, one __syncthreads per chunk (R8-proven pattern).
extern __shared__ char smc[];

__global__ __launch_bounds__(NT, 2) void fused_kernel(
    const float* __restrict__ x, const float* __restrict__ bias,
    float* __restrict__ out) {
    const uint32_t sb = smem_u32(smc);
    const int t = threadIdx.x;
    const int wid = t >> 5, lane = t & 31;

    const int row0 = blockIdx.x * BM;
    const int batch = row0 >> 15;
    const int rlocal0 = row0 & (ROWS_PER_BATCH - 1);
    const float mean = g_mean[batch];
    const float rstd = g_rstd[batch];

    const float4* v4 = reinterpret_cast<const float4*>(
        x + (size_t)batch * BATCH_STRIDE + NV + (size_t)rlocal0 * WD);
    const char* whp = reinterpret_cast<const char*>(g_Wh);

    // pre-issue B chunks 0,1 (1024 cp16 each = 4/thread)
#pragma unroll
    for (int s0 = 0; s0 < 2; s0++) {
#pragma unroll
        for (int r = 0; r < 4; r++) {
            int idx = r * NT + t;
            int o = idx >> 2, ku = idx & 3;   // 64B rows (k=32)
            uint32_t off = (uint32_t)(o * 64) +
                           ((uint32_t)(ku * 16) ^ (((uint32_t)(o >> 1) & 3) << 4));
            cp16(sb + SMEM_BS(s0) + off, whp + o * 512 + s0 * 64 + ku * 16);
        }
        CP_COMMIT();
    }

    // c1[o] = bias[o] + 1 - mean*rstd*Wsum[o]
    {
        float c = bias[t] + 1.f - mean * rstd * g_Wsum[t];
        reinterpret_cast<float*>(smc + SMEM_C1)[t] = c;
    }

    // A: load v fp32 (64x256), cvt fp16, STS swizzled ([m][k], 512B rows)
#pragma unroll
    for (int r = 0; r < 16; r++) {
        int idx = r * NT + t;                 // 4096 float4
        int m = idx >> 6, j4 = idx & 63;      // 64 float4 per row
        float4 f = v4[m * 64 + j4];
        uint2 h = make_uint2(pack_f16x2(f.x, f.y), pack_f16x2(f.z, f.w));
        uint32_t off = (uint32_t)(m * 512) +
                       (((uint32_t)((j4 >> 1) * 16)) ^ (((uint32_t)m & 7) << 4)) +
                       (uint32_t)((j4 & 1) * 8);
        *reinterpret_cast<uint2*>(smc + SMEM_A + off) = h;
    }

    const int wm = (wid & 1) * 32;            // 2 m-warps
    const int wn = (wid >> 1) * 64;           // 4 n-warps
    const int lg = lane >> 3, lr = lane & 7;

    float acc[2][8][4];
#pragma unroll
    for (int i = 0; i < 2; i++)
#pragma unroll
        for (int j = 0; j < 8; j++)
#pragma unroll
            for (int q = 0; q < 4; q++) acc[i][j][q] = 0.f;

#pragma unroll 1
    for (int c = 0; c < NCH; c++) {
        if (c < NCH - 1) CP_WAIT(1); else CP_WAIT(0);
        __syncthreads();   // chunk c ready; all warps done with stage (c-1)%3

        // issue chunk c+2 into stage (c+2)%3 (drained, proven by the sync)
        if (c < NCH - 2) {
            const uint32_t Bn = sb + SMEM_BS((c + 2) % 3);
            const int kb = (c + 2) * 64;      // byte offset in 512B W row
#pragma unroll
            for (int r = 0; r < 4; r++) {
                int idx = r * NT + t;
                int o = idx >> 2, ku = idx & 3;
                uint32_t off = (uint32_t)(o * 64) +
                               ((uint32_t)(ku * 16) ^ (((uint32_t)(o >> 1) & 3) << 4));
                cp16(Bn + off, whp + o * 512 + kb + ku * 16);
            }
            CP_COMMIT();
        }

        // compute chunk c (2 ksteps of 16) from stage c%3
        const uint32_t Bb = sb + SMEM_BS(c % 3);
#pragma unroll
        for (int ks = 0; ks < 2; ks++) {
            const int kl = ks * 16;
            const int kg = c * KCH + kl;
            uint32_t af[2][4];
#pragma unroll
            for (int i = 0; i < 2; i++) {
                int am = wm + i * 16 + ((lg & 1) << 3) + lr;
                int ak = kg + ((lg >> 1) << 3);
                uint32_t off = (uint32_t)(am * 512) +
                               (((uint32_t)(ak * 2)) ^ (((uint32_t)am & 7) << 4));
                ldsm_x4(af[i][0], af[i][1], af[i][2], af[i][3], sb + SMEM_A + off);
            }
#pragma unroll
            for (int p = 0; p < 4; p++) {
                int bn = wn + p * 16 + ((lg >> 1) << 3) + lr;
                int bk = kl + ((lg & 1) << 3);   // within-chunk k
                uint32_t off = (uint32_t)(bn * 64) +
                               ((uint32_t)(bk * 2) ^ (((uint32_t)(bn >> 1) & 3) << 4));
                uint32_t b0, b1, b2, b3;
                ldsm_x4(b0, b1, b2, b3, Bb + off);
#pragma unroll
                for (int i = 0; i < 2; i++) {
                    mma16816(acc[i][p * 2 + 0], af[i], b0, b1);
                    mma16816(acc[i][p * 2 + 1], af[i], b2, b3);
                }
            }
        }
    }

    // epilogue: out = u * (acc*rstd + c1[col])
    {
        const int qr = lane >> 2;
        const int qc = (lane & 3) * 2;
        const float* uBase =
            x + (size_t)batch * BATCH_STRIDE + (size_t)rlocal0 * WD;
        const float* c1 = reinterpret_cast<const float*>(smc + SMEM_C1);
#pragma unroll
        for (int i = 0; i < 2; i++) {
#pragma unroll
            for (int half = 0; half < 2; half++) {
                const int lrow = wm + i * 16 + qr + half * 8;
                const float* up = uBase + (size_t)lrow * WD;
                float* op = out + (size_t)(row0 + lrow) * WD;
#pragma unroll
                for (int j = 0; j < 8; j++) {
                    const int col = wn + j * 8 + qc;
                    float2 u2 = *reinterpret_cast<const float2*>(up + col);
                    float2 cc = *reinterpret_cast<const float2*>(c1 + col);
                    float d0 = acc[i][j][half * 2 + 0];
                    float d1 = acc[i][j][half * 2 + 1];
                    float2 r;
                    r.x = u2.x * fmaf(d0, rstd, cc.x);
                    r.y = u2.y * fmaf(d1, rstd, cc.y);
                    *reinterpret_cast<float2*>(op + col) = r;
                }
            }
        }
    }
}

// ---------------- launch ----------------
extern "C" void kernel_launch(void* const* d_in, const int* in_sizes, int n_in,
                              void* d_out, int out_size) {
    const float* x = (const float*)d_in[0];
    const float* W = (const float*)d_in[1];
    const float* b = (const float*)d_in[2];
    float* out = (float*)d_out;

    w_prep_kernel<<<WD, 256>>>(W);
    reduce_pass1<<<dim3(NCHUNK, B_), 256>>>(x);
    reduce_pass2<<<B_, 256>>>();

    cudaFuncSetAttribute(fused_kernel,
                         cudaFuncAttributeMaxDynamicSharedMemorySize, SMEM_TOTAL);
    fused_kernel<<<M_TOTAL / BM, NT, SMEM_TOTAL>>>(x, b, out);
}

// round 10
// speedup vs baseline: 1.0996x; 1.0996x over previous
#include <cuda_runtime.h>
#include <cuda_fp16.h>
#include <cstdint>

// Problem: x [8,256,256,256] fp32, W [256,256], b [256]
//   u = x[:,:128], v = x[:,128:]; per-batch LayerNorm(v); v@W^T+b; out=u*(v+1)
// LayerNorm deferred to epilogue: vnorm@W^T = rstd*(v@W^T) - mean*rstd*rowsum(W)
#define B_              8
#define WD              256
#define ROWS_PER_BATCH  32768
#define M_TOTAL         262144
#define NV              8388608
#define BATCH_STRIDE    (2 * NV)
#define NCHUNK          512
#define EPS             1e-5f

#define BM   128          // rows per CTA
#define BN   128          // cols per CTA (half of WD)
#define NT   256          // 8 warps

// SMEM (bytes): c1 (128 floats), A 3-stage (16KB each), B resident (64KB).
// Epilogue reuses the A region as a 64x544B fp32 staging buffer (34816 B).
#define SMEM_C1    0
#define SMEM_A(s)  (1024 + (s) * 16384)
#define SMEM_STAGE 1024
#define SMEM_B     (1024 + 3 * 16384)
#define SMEM_TOTAL (SMEM_B + 65536)      // 115712; x2 CTAs/SM = full carveout

// ---------------- device scratch ----------------
__device__ float  g_partS[B_ * NCHUNK];
__device__ float  g_partQ[B_ * NCHUNK];
__device__ float  g_mean[B_];
__device__ float  g_rstd[B_];
__device__ float  g_Wsum[WD];
__device__ __half g_Wh[WD * WD];
__device__ __half g_vh[(size_t)M_TOTAL * WD];   // raw v, fp16 (written by pass1)

// ---------------- helpers ----------------
__device__ __forceinline__ uint32_t smem_u32(const void* p) {
    uint32_t a;
    asm("{ .reg .u64 t; cvta.to.shared.u64 t, %1; cvt.u32.u64 %0, t; }"
        : "=r"(a) : "l"(p));
    return a;
}
__device__ __forceinline__ uint32_t pack_f16x2(float lo, float hi) {
    uint32_t r;
    asm("cvt.rn.f16x2.f32 %0, %1, %2;" : "=r"(r) : "f"(hi), "f"(lo));
    return r;
}
__device__ __forceinline__ void cp16(uint32_t dst, const void* src) {
    asm volatile("cp.async.cg.shared.global [%0], [%1], 16;" :: "r"(dst), "l"(src));
}
#define CP_COMMIT() asm volatile("cp.async.commit_group;" ::: "memory")
#define CP_WAIT(n)  asm volatile("cp.async.wait_group %0;" :: "n"(n) : "memory")
__device__ __forceinline__ void ldsm_x4(uint32_t& r0, uint32_t& r1, uint32_t& r2,
                                        uint32_t& r3, uint32_t addr) {
    asm volatile("ldmatrix.sync.aligned.m8n8.x4.shared.b16 {%0,%1,%2,%3}, [%4];"
                 : "=r"(r0), "=r"(r1), "=r"(r2), "=r"(r3) : "r"(addr));
}
__device__ __forceinline__ void mma16816(float* d, const uint32_t* a,
                                         uint32_t b0, uint32_t b1) {
    asm volatile(
        "mma.sync.aligned.m16n8k16.row.col.f32.f16.f16.f32 "
        "{%0,%1,%2,%3}, {%4,%5,%6,%7}, {%8,%9}, {%0,%1,%2,%3};"
        : "+f"(d[0]), "+f"(d[1]), "+f"(d[2]), "+f"(d[3])
        : "r"(a[0]), "r"(a[1]), "r"(a[2]), "r"(a[3]), "r"(b0), "r"(b1));
}

// ---------------- W prep: fp16 convert + row sums (tiny) ----------------
__global__ __launch_bounds__(256) void w_prep_kernel(const float* __restrict__ W) {
    const int o = blockIdx.x, t = threadIdx.x;
    float w = W[o * WD + t];
    g_Wh[o * WD + t] = __float2half_rn(w);
    float s = w;
#pragma unroll
    for (int off = 16; off > 0; off >>= 1) s += __shfl_xor_sync(0xffffffffu, s, off);
    __shared__ float ss[8];
    if ((t & 31) == 0) ss[t >> 5] = s;
    __syncthreads();
    if (t == 0) {
        float S = 0.f;
#pragma unroll
        for (int w8 = 0; w8 < 8; w8++) S += ss[w8];
        g_Wsum[o] = S;
    }
}

// ---------------- pass 1: stats + v -> fp16 copy ----------------
__global__ __launch_bounds__(256) void reduce_pass1(const float* __restrict__ x) {
    const int b = blockIdx.y;
    const int chunk = blockIdx.x;
    const float4* v4 =
        reinterpret_cast<const float4*>(x + (size_t)b * BATCH_STRIDE + NV);
    uint2* vh2 = reinterpret_cast<uint2*>(g_vh + (size_t)b * NV);
    const int base = chunk * 4096 + threadIdx.x;
    float s = 0.f, q = 0.f;
#pragma unroll
    for (int i = 0; i < 16; i++) {
        float4 t = v4[base + i * 256];
        s += (t.x + t.y) + (t.z + t.w);
        q += t.x * t.x + t.y * t.y + t.z * t.z + t.w * t.w;
        vh2[base + i * 256] =
            make_uint2(pack_f16x2(t.x, t.y), pack_f16x2(t.z, t.w));
    }
#pragma unroll
    for (int off = 16; off > 0; off >>= 1) {
        s += __shfl_xor_sync(0xffffffffu, s, off);
        q += __shfl_xor_sync(0xffffffffu, q, off);
    }
    __shared__ float ss[8], qs[8];
    const int warp = threadIdx.x >> 5, lane = threadIdx.x & 31;
    if (lane == 0) { ss[warp] = s; qs[warp] = q; }
    __syncthreads();
    if (threadIdx.x == 0) {
        float S = 0.f, Q = 0.f;
#pragma unroll
        for (int w = 0; w < 8; w++) { S += ss[w]; Q += qs[w]; }
        g_partS[b * NCHUNK + chunk] = S;
        g_partQ[b * NCHUNK + chunk] = Q;
    }
}

__global__ __launch_bounds__(256) void reduce_pass2() {
    const int b = blockIdx.x;
    float s = g_partS[b * NCHUNK + threadIdx.x] +
              g_partS[b * NCHUNK + 256 + threadIdx.x];
    float q = g_partQ[b * NCHUNK + threadIdx.x] +
              g_partQ[b * NCHUNK + 256 + threadIdx.x];
#pragma unroll
    for (int off = 16; off > 0; off >>= 1) {
        s += __shfl_xor_sync(0xffffffffu, s, off);
        q += __shfl_xor_sync(0xffffffffu, q, off);
    }
    __shared__ float ss[8], qs[8];
    const int warp = threadIdx.x >> 5, lane = threadIdx.x & 31;
    if (lane == 0) { ss[warp] = s; qs[warp] = q; }
    __syncthreads();
    if (threadIdx.x == 0) {
        float S = 0.f, Q = 0.f;
#pragma unroll
        for (int w = 0; w < 8; w++) { S += ss[w]; Q += qs[w]; }
        const float inv_n = 1.0f / (float)NV;
        float mean = S * inv_n;
        float var = Q * inv_n - mean * mean;
        g_mean[b] = mean;
        g_rstd[b] = rsqrtf(var + EPS);
    }
}

// ---------------- fused GEMM + gating ----------------
// CTA 128x128, 8 warps (warp tile 32x64), 2 CTAs/SM.
// B (W half, 64KB) smem-resident; A 3-stage cp.async pipeline, 1 sync/chunk.
// Epilogue: fp32 smem staging -> fully coalesced u/out traffic.
extern __shared__ char smc[];

__global__ __launch_bounds__(NT, 2) void fused_kernel(
    const float* __restrict__ x, const float* __restrict__ bias,
    float* __restrict__ out) {
    const uint32_t sb = smem_u32(smc);
    const int t = threadIdx.x;
    const int wid = t >> 5, lane = t & 31;

    const int nb = blockIdx.x;              // 0/1: which 128-col half of W
    const int row0 = blockIdx.y * BM;
    const int batch = row0 >> 15;
    const int rlocal0 = row0 & (ROWS_PER_BATCH - 1);
    const float mean = g_mean[batch];
    const float rstd = g_rstd[batch];

    const char* vhp = reinterpret_cast<const char*>(g_vh + (size_t)row0 * WD);
    const char* whp =
        reinterpret_cast<const char*>(g_Wh + (size_t)(nb * BN) * WD);

    // c1[o] = bias[o] + 1 - mean*rstd*Wsum[o]
    if (t < BN) {
        int col = nb * BN + t;
        reinterpret_cast<float*>(smc + SMEM_C1)[t] =
            bias[col] + 1.f - mean * rstd * g_Wsum[col];
    }

    // group 0: B resident (4096 x 16B) + A chunk 0 (1024 x 16B)
#pragma unroll
    for (int r = 0; r < 16; r++) {
        int idx = r * NT + t;
        int o = idx >> 5, ku = idx & 31;    // 512B rows (k=256)
        uint32_t off = (uint32_t)(o * 512 + ku * 16) ^ ((uint32_t)(o & 7) << 4);
        cp16(sb + SMEM_B + off, whp + o * 512 + ku * 16);
    }
#pragma unroll
    for (int r = 0; r < 4; r++) {
        int idx = r * NT + t;
        int m = idx >> 3, ku = idx & 7;     // 128B rows (k=64)
        uint32_t off = (uint32_t)(m * 128 + ku * 16) ^ ((uint32_t)(m & 7) << 4);
        cp16(sb + SMEM_A(0) + off, vhp + m * 512 + ku * 16);
    }
    CP_COMMIT();
    // group 1: A chunk 1
#pragma unroll
    for (int r = 0; r < 4; r++) {
        int idx = r * NT + t;
        int m = idx >> 3, ku = idx & 7;
        uint32_t off = (uint32_t)(m * 128 + ku * 16) ^ ((uint32_t)(m & 7) << 4);
        cp16(sb + SMEM_A(1) + off, vhp + m * 512 + 128 + ku * 16);
    }
    CP_COMMIT();

    const int wm = (wid & 3) * 32;          // warp m base (4 warps)
    const int wn = (wid >> 2) * 64;         // warp n base (2 warps)
    const int lg = lane >> 3, lr = lane & 7;

    float acc[2][8][4];
#pragma unroll
    for (int i = 0; i < 2; i++)
#pragma unroll
        for (int j = 0; j < 8; j++)
#pragma unroll
            for (int q = 0; q < 4; q++) acc[i][j][q] = 0.f;

#pragma unroll 1
    for (int c = 0; c < 4; c++) {
        if (c < 3) CP_WAIT(1); else CP_WAIT(0);
        __syncthreads();   // all warps done with buffer (c-1)%3 and chunk c ready

        // issue chunk c+2 into stage (c+2)%3 (drained by the sync above)
        if (c < 2) {
            const uint32_t An = sb + SMEM_A((c + 2) % 3);
            const int kb = (c + 2) * 128;
#pragma unroll
            for (int r = 0; r < 4; r++) {
                int idx = r * NT + t;
                int m = idx >> 3, ku = idx & 7;
                uint32_t off = (uint32_t)(m * 128 + ku * 16) ^ ((uint32_t)(m & 7) << 4);
                cp16(An + off, vhp + m * 512 + kb + ku * 16);
            }
            CP_COMMIT();
        }

        // compute chunk c from stage c%3
        const uint32_t Ab = sb + SMEM_A(c % 3);
#pragma unroll
        for (int ks = 0; ks < 4; ks++) {
            const int kl = ks * 16;
            uint32_t af[2][4];
#pragma unroll
            for (int i = 0; i < 2; i++) {
                int am = wm + i * 16 + ((lg & 1) << 3) + lr;
                int ak = kl + ((lg >> 1) << 3);
                uint32_t off = (uint32_t)(am * 128 + ak * 2) ^ ((uint32_t)(am & 7) << 4);
                ldsm_x4(af[i][0], af[i][1], af[i][2], af[i][3], Ab + off);
            }
#pragma unroll
            for (int p = 0; p < 4; p++) {
                int bn = wn + p * 16 + ((lg >> 1) << 3) + lr;
                int bk = c * 64 + kl + ((lg & 1) << 3);
                uint32_t off = (uint32_t)(bn * 512 + bk * 2) ^ ((uint32_t)(bn & 7) << 4);
                uint32_t b0, b1, b2, b3;
                ldsm_x4(b0, b1, b2, b3, sb + SMEM_B + off);
#pragma unroll
                for (int i = 0; i < 2; i++) {
                    mma16816(acc[i][p * 2 + 0], af[i], b0, b1);
                    mma16816(acc[i][p * 2 + 1], af[i], b2, b3);
                }
            }
        }
    }

    // ---- epilogue: stage P (fp32) in smem, then fully coalesced gating ----
    // Two 64-row passes; stage row stride 544B (512+32) -> STS.64 is 2-wavefront
    // minimal; final LDS/LDG/STG are 512B-contiguous per warp instruction.
    {
        const int qr = lane >> 2;
        const int qc = (lane & 3) * 2;
        const int colbase = nb * BN;
        const int lane5 = t & 31, rg = t >> 5;
        const float* c1 = reinterpret_cast<const float*>(smc + SMEM_C1);
        const float* uBase =
            x + (size_t)batch * BATCH_STRIDE + (size_t)rlocal0 * WD + colbase;
        const float4 c4 = *reinterpret_cast<const float4*>(c1 + lane5 * 4);

#pragma unroll 1
        for (int pass = 0; pass < 2; pass++) {
            __syncthreads();   // mainloop done / previous pass consumed
            if ((wm >> 6) == pass) {        // warps owning rows [pass*64, +64)
                const int wml = wm & 63;
#pragma unroll
                for (int i = 0; i < 2; i++)
#pragma unroll
                    for (int half = 0; half < 2; half++) {
                        const int row = wml + i * 16 + half * 8 + qr;
#pragma unroll
                        for (int j = 0; j < 8; j++) {
                            const int col = wn + j * 8 + qc;
                            float2 dv = make_float2(acc[i][j][half * 2 + 0],
                                                    acc[i][j][half * 2 + 1]);
                            *reinterpret_cast<float2*>(
                                smc + SMEM_STAGE + row * 544 + col * 4) = dv;
                        }
                    }
            }
            __syncthreads();
#pragma unroll
            for (int it = 0; it < 8; it++) {
                const int row = it * 8 + rg;          // local 0..63
                const int grow = pass * 64 + row;     // CTA-local row
                float4 d4 = *reinterpret_cast<const float4*>(
                    smc + SMEM_STAGE + row * 544 + lane5 * 16);
                float4 u4 = *reinterpret_cast<const float4*>(
                    uBase + (size_t)grow * WD + lane5 * 4);
                float4 r;
                r.x = u4.x * fmaf(d4.x, rstd, c4.x);
                r.y = u4.y * fmaf(d4.y, rstd, c4.y);
                r.z = u4.z * fmaf(d4.z, rstd, c4.z);
                r.w = u4.w * fmaf(d4.w, rstd, c4.w);
                *reinterpret_cast<float4*>(
                    out + (size_t)(row0 + grow) * WD + colbase + lane5 * 4) = r;
            }
        }
    }
}

// ---------------- launch ----------------
extern "C" void kernel_launch(void* const* d_in, const int* in_sizes, int n_in,
                              void* d_out, int out_size) {
    const float* x = (const float*)d_in[0];
    const float* W = (const float*)d_in[1];
    const float* b = (const float*)d_in[2];
    float* out = (float*)d_out;

    w_prep_kernel<<<WD, 256>>>(W);
    reduce_pass1<<<dim3(NCHUNK, B_), 256>>>(x);
    reduce_pass2<<<B_, 256>>>();

    cudaFuncSetAttribute(fused_kernel,
                         cudaFuncAttributeMaxDynamicSharedMemorySize, SMEM_TOTAL);
    fused_kernel<<<dim3(2, M_TOTAL / BM), NT, SMEM_TOTAL>>>(x, b, out);
}